// round 15
// baseline (speedup 1.0000x reference)
#include <cuda_runtime.h>
#include <cuda_bf16.h>
#include <stdint.h>

#define NROWS   65536
#define DDIM    256
#define KCODES  1024
#define LLEV    8
#define TILE_M  64
#define THREADS 256
#define NWARPS  8
#define CBUF    32
#define EPS     3e-3f
#define TSTRIDE 65

__device__ double g_loss[LLEV];
__device__ float  g_norms[LLEV * KCODES];
// fragment-linear bf16 codebook: [(lvl*8+pass)*16+ks][nfg*32+lane] uint2
__device__ __align__(16) uint2 g_B[(size_t)LLEV * 8 * 16 * 512];

// residual tile index (row r, dim dd) — conflict-free for all phases
#define TIX(r, dd) (((dd) * TSTRIDE) + (r) + ((((dd) >> 6) & 3) << 3))

// smem layout (bytes)
#define SM_A    0                     // 32768: A plane uint4[4*16*32]
#define SM_TILE 32768                 // 66816: float[DDIM*TSTRIDE+64]
#define SM_BS   99584                 // 4096
#define SM_AS   103680                // 256
#define SM_WMV  103936                // 1024: float[64][4]
#define SM_THR  104960                // 256
#define SM_CNT  105216                // 256
#define SM_CAND 105472                // 4096: uint16[64][32]
#define SM_BEST 109568                // 512: uint64[64]
#define SM_IDX  110080                // 256
#define SM_RED  110336                // 64
#define SMEM_BYTES 110400

__device__ __forceinline__ void mma16816(float* c, const uint4 a, const uint2 b) {
    asm volatile("mma.sync.aligned.m16n8k16.row.col.f32.bf16.bf16.f32 "
        "{%0,%1,%2,%3},{%4,%5,%6,%7},{%8,%9},{%0,%1,%2,%3};"
        : "+f"(c[0]), "+f"(c[1]), "+f"(c[2]), "+f"(c[3])
        : "r"(a.x), "r"(a.y), "r"(a.z), "r"(a.w), "r"(b.x), "r"(b.y));
}

// 3-deep min-list insert
__device__ __forceinline__ void ins3(float v, int k,
                                     float& m1, int& i1, float& m2, int& i2, float& m3, int& i3) {
    if (v < m3) {
        if (v < m2) {
            m3 = m2; i3 = i2;
            if (v < m1) { m2 = m1; i2 = i1; m1 = v; i1 = k; }
            else        { m2 = v;  i2 = k; }
        } else { m3 = v; i3 = k; }
    }
}

// ---------------- prep ----------------
__global__ void rvq_zero_kernel() { if (threadIdx.x < LLEV) g_loss[threadIdx.x] = 0.0; }

__global__ void rvq_norms_kernel(const float* __restrict__ emb) {
    int warp = (blockIdx.x * blockDim.x + threadIdx.x) >> 5;
    int lane = threadIdx.x & 31;
    if (warp >= LLEV * KCODES) return;
    const float* e = emb + (size_t)warp * DDIM;
    float s = 0.f;
    #pragma unroll
    for (int i = 0; i < DDIM / 32; ++i) { float v = e[lane + 32 * i]; s = __fmaf_rn(v, v, s); }
    #pragma unroll
    for (int o = 16; o; o >>= 1) s += __shfl_xor_sync(0xFFFFFFFFu, s, o);
    if (lane == 0) g_norms[warp] = s;
}

__global__ void rvq_packB_kernel(const float* __restrict__ emb) {
    int b = blockIdx.x;                  // (lvl*8+p)*16+ks
    int lvl = b >> 7, p = (b >> 4) & 7, ks = b & 15;
    for (int pid = threadIdx.x; pid < 512; pid += blockDim.x) {
        int nf = pid >> 5, lane = pid & 31;
        int code = p * 128 + nf * 8 + (lane >> 2);
        int kb   = ks * 16 + 2 * (lane & 3);
        const float* e = emb + ((size_t)lvl * KCODES + code) * DDIM + kb;
        uint16_t h0 = __bfloat16_as_ushort(__float2bfloat16(e[0]));
        uint16_t h1 = __bfloat16_as_ushort(__float2bfloat16(e[1]));
        uint16_t h2 = __bfloat16_as_ushort(__float2bfloat16(e[8]));
        uint16_t h3 = __bfloat16_as_ushort(__float2bfloat16(e[9]));
        g_B[(size_t)b * 512 + nf * 32 + lane] =
            make_uint2((uint32_t)h0 | ((uint32_t)h1 << 16),
                       (uint32_t)h2 | ((uint32_t)h3 << 16));
    }
}

// ---------------- main ----------------
__global__ void __launch_bounds__(THREADS, 2)
rvq_mma_kernel(const float* __restrict__ x, const float* __restrict__ emb,
               float* __restrict__ out, long long out_size)
{
    extern __shared__ char smem[];
    uint4*     Ah   = (uint4*)(smem + SM_A);
    float*     T    = (float*)(smem + SM_TILE);
    float*     b_s  = (float*)(smem + SM_BS);
    float*     a_s  = (float*)(smem + SM_AS);
    float*     wmv  = (float*)(smem + SM_WMV);
    float*     thr_s = (float*)(smem + SM_THR);
    uint32_t*  cnt  = (uint32_t*)(smem + SM_CNT);
    uint16_t*  cand = (uint16_t*)(smem + SM_CAND);
    unsigned long long* best = (unsigned long long*)(smem + SM_BEST);
    int*       idx_s = (int*)(smem + SM_IDX);
    double*    red  = (double*)(smem + SM_RED);

    const int tid = threadIdx.x, wid = tid >> 5, lane = tid & 31;
    const int mg = wid & 1, ng = wid >> 1;       // 2 m-groups x 4 n-groups
    const int rowbase = blockIdx.x * TILE_M;
    const int d = tid;                           // split/update: dim
    const int di = d & 15, sk = d >> 4;
    const int lane_dp = (di & 7) >> 1, word_dp = 2 * (di >> 3), half = di & 1;

    // ---- lvl-0 load: x -> tile + A plane ----
    #pragma unroll 4
    for (int r = 0; r < TILE_M; ++r) {
        float v = x[(size_t)(rowbase + r) * DDIM + d];
        T[TIX(r, d)] = v;
        uint16_t h = __bfloat16_as_ushort(__float2bfloat16(v));
        int ri = r & 15, mtg = r >> 4;
        int ln = (ri & 7) * 4 + lane_dp;
        int w  = (ri >> 3) + word_dp;
        ((uint16_t*)Ah)[((((mtg * 16 + sk) * 32 + ln) * 4 + w) * 2) + half] = h;
    }
    __syncthreads();

    for (int lvl = 0; lvl < LLEV; ++lvl) {
        // ---- row norms from tile (bit-exact tree) ----
        {
            int r = tid >> 2, p = tid & 3;
            float s = 0.f;
            #pragma unroll 8
            for (int j = 0; j < 64; ++j) {
                float v = T[TIX(r, p * 64 + j)];
                s = __fmaf_rn(v, v, s);
            }
            s += __shfl_xor_sync(0xFFFFFFFFu, s, 1);
            s += __shfl_xor_sync(0xFFFFFFFFu, s, 2);
            if (p == 0) a_s[r] = s;
        }
        #pragma unroll
        for (int i = 0; i < KCODES / THREADS; ++i)
            b_s[tid + THREADS * i] = g_norms[lvl * KCODES + tid + THREADS * i];
        if (tid < TILE_M) { cnt[tid] = 0u; best[tid] = ~0ull; }
        __syncthreads();

        float a8[2][2];
        #pragma unroll
        for (int mt = 0; mt < 2; ++mt)
            #pragma unroll
            for (int h2 = 0; h2 < 2; ++h2)
                a8[mt][h2] = a_s[mg * 32 + mt * 16 + h2 * 8 + (lane >> 2)];

        // ======== single GEMM pass with per-thread top-3 tracking ========
        float m1[2][2], m2[2][2], m3[2][2];
        int   i1[2][2], i2[2][2], i3[2][2];
        #pragma unroll
        for (int mt = 0; mt < 2; ++mt)
            #pragma unroll
            for (int h2 = 0; h2 < 2; ++h2) {
                m1[mt][h2] = m2[mt][h2] = m3[mt][h2] = 3.4028235e38f;
                i1[mt][h2] = i2[mt][h2] = i3[mt][h2] = 0;
            }

        for (int it = 0; it < 8; ++it) {
            float acc[2][4][4];
            #pragma unroll
            for (int a = 0; a < 2; ++a)
                #pragma unroll
                for (int b = 0; b < 4; ++b)
                    #pragma unroll
                    for (int c = 0; c < 4; ++c) acc[a][b][c] = 0.f;
            const uint2* gb = g_B + (size_t)((lvl * 8 + it) * 16) * 512;
            #pragma unroll 4
            for (int s = 0; s < 16; ++s) {
                uint4 ah[2];
                #pragma unroll
                for (int mt = 0; mt < 2; ++mt)
                    ah[mt] = Ah[((mg * 2 + mt) * 16 + s) * 32 + lane];
                const uint2* gs = gb + (size_t)s * 512;
                #pragma unroll
                for (int nf = 0; nf < 4; ++nf) {
                    uint2 bh = gs[(ng * 4 + nf) * 32 + lane];
                    mma16816(acc[0][nf], ah[0], bh);
                    mma16816(acc[1][nf], ah[1], bh);
                }
            }
            #pragma unroll
            for (int mt = 0; mt < 2; ++mt)
                #pragma unroll
                for (int h2 = 0; h2 < 2; ++h2) {
                    #pragma unroll
                    for (int nf = 0; nf < 4; ++nf) {
                        int k0 = it * 128 + ng * 32 + nf * 8 + 2 * (lane & 3);
                        float dA = __fmaf_rn(-2.0f, acc[mt][nf][h2 * 2],     __fadd_rn(a8[mt][h2], b_s[k0]));
                        float dB = __fmaf_rn(-2.0f, acc[mt][nf][h2 * 2 + 1], __fadd_rn(a8[mt][h2], b_s[k0 + 1]));
                        ins3(dA, k0,     m1[mt][h2], i1[mt][h2], m2[mt][h2], i2[mt][h2], m3[mt][h2], i3[mt][h2]);
                        ins3(dB, k0 + 1, m1[mt][h2], i1[mt][h2], m2[mt][h2], i2[mt][h2], m3[mt][h2], i3[mt][h2]);
                    }
                }
        }
        // row min (from m1) across quad lanes + 4 ng warps
        #pragma unroll
        for (int mt = 0; mt < 2; ++mt)
            #pragma unroll
            for (int h2 = 0; h2 < 2; ++h2) {
                float v = m1[mt][h2];
                v = fminf(v, __shfl_xor_sync(0xFFFFFFFFu, v, 1));
                v = fminf(v, __shfl_xor_sync(0xFFFFFFFFu, v, 2));
                if ((lane & 3) == 0) {
                    int row = mg * 32 + mt * 16 + h2 * 8 + (lane >> 2);
                    wmv[row * 4 + ng] = v;
                }
            }
        __syncthreads();
        if (tid < TILE_M) {
            float v = fminf(fminf(wmv[tid * 4], wmv[tid * 4 + 1]),
                            fminf(wmv[tid * 4 + 2], wmv[tid * 4 + 3]));
            thr_s[tid] = v + EPS;
        }
        __syncthreads();

        // ---- candidate append from registers (no second GEMM) ----
        #pragma unroll
        for (int mt = 0; mt < 2; ++mt)
            #pragma unroll
            for (int h2 = 0; h2 < 2; ++h2) {
                int row = mg * 32 + mt * 16 + h2 * 8 + (lane >> 2);
                float thr = thr_s[row];
                if (m1[mt][h2] <= thr) {
                    uint32_t pos = atomicAdd(&cnt[row], 1u);
                    if (pos < CBUF) cand[row * CBUF + pos] = (uint16_t)i1[mt][h2];
                }
                if (m2[mt][h2] <= thr) {
                    uint32_t pos = atomicAdd(&cnt[row], 1u);
                    if (pos < CBUF) cand[row * CBUF + pos] = (uint16_t)i2[mt][h2];
                }
                if (m3[mt][h2] <= thr)
                    atomicAdd(&cnt[row], 1000u);   // force exact full scan (rare)
            }
        __syncthreads();

        // ---- exact refine (lexicographic (dist,index)); residual from tile ----
        const float* Eb = emb + (size_t)lvl * KCODES * DDIM;
        for (int row = wid; row < TILE_M; row += NWARPS) {
            uint32_t n = cnt[row];
            float ar = a_s[row];
            unsigned long long bp = ~0ull;
            if (n <= CBUF) {
                for (uint32_t c = lane; c < n; c += 32) {
                    int k = cand[row * CBUF + c];
                    const float4* e4 = (const float4*)(Eb + (size_t)k * DDIM);
                    float s = 0.f;
                    #pragma unroll 8
                    for (int q = 0; q < DDIM / 4; ++q) {
                        float4 ev = e4[q];
                        s = __fmaf_rn(T[TIX(row, 4 * q + 0)], ev.x, s);
                        s = __fmaf_rn(T[TIX(row, 4 * q + 1)], ev.y, s);
                        s = __fmaf_rn(T[TIX(row, 4 * q + 2)], ev.z, s);
                        s = __fmaf_rn(T[TIX(row, 4 * q + 3)], ev.w, s);
                    }
                    float dist = __fmaf_rn(-2.0f, s, __fadd_rn(ar, b_s[k]));
                    unsigned long long p = ((unsigned long long)__float_as_uint(dist) << 32) | (uint32_t)k;
                    if (p < bp) bp = p;
                }
            } else {
                for (int k = lane; k < KCODES; k += 32) {
                    const float4* e4 = (const float4*)(Eb + (size_t)k * DDIM);
                    float s = 0.f;
                    #pragma unroll 8
                    for (int q = 0; q < DDIM / 4; ++q) {
                        float4 ev = e4[q];
                        s = __fmaf_rn(T[TIX(row, 4 * q + 0)], ev.x, s);
                        s = __fmaf_rn(T[TIX(row, 4 * q + 1)], ev.y, s);
                        s = __fmaf_rn(T[TIX(row, 4 * q + 2)], ev.z, s);
                        s = __fmaf_rn(T[TIX(row, 4 * q + 3)], ev.w, s);
                    }
                    float dist = __fmaf_rn(-2.0f, s, __fadd_rn(ar, b_s[k]));
                    unsigned long long p = ((unsigned long long)__float_as_uint(dist) << 32) | (uint32_t)k;
                    if (p < bp) bp = p;
                }
            }
            #pragma unroll
            for (int o = 16; o; o >>= 1) {
                unsigned long long op = __shfl_xor_sync(0xFFFFFFFFu, bp, o);
                if (op < bp) bp = op;
            }
            if (lane == 0) best[row] = bp;
        }
        __syncthreads();

        if (tid < TILE_M) {
            int ix = (int)(uint32_t)(best[tid] & 0xFFFFFFFFu);
            idx_s[tid] = ix;
            long long ib = (long long)NROWS * DDIM + 1 +
                           ((long long)(rowbase + tid) * LLEV + lvl);
            if (ib < out_size) out[ib] = (float)ix;
        }
        __syncthreads();

        // ---- update (exact fp32 chain) fused with next level's split ----
        double lacc = 0.0;
        const bool more = (lvl + 1 < LLEV);
        #pragma unroll 4
        for (int r = 0; r < TILE_M; ++r) {
            int code = idx_s[r];
            float q  = Eb[(size_t)code * DDIM + d];
            float rv = T[TIX(r, d)];
            float df = __fsub_rn(q, rv);
            float qs = __fadd_rn(rv, df);
            lacc = __fma_rn((double)df, (double)df, lacc);
            float nr = __fsub_rn(rv, qs);
            T[TIX(r, d)] = nr;
            size_t off = (size_t)(rowbase + r) * DDIM + d;
            out[off] = lvl ? __fadd_rn(out[off], qs) : qs;
            if (more) {
                uint16_t h = __bfloat16_as_ushort(__float2bfloat16(nr));
                int ri = r & 15, mtg = r >> 4;
                int ln = (ri & 7) * 4 + lane_dp;
                int w  = (ri >> 3) + word_dp;
                ((uint16_t*)Ah)[((((mtg * 16 + sk) * 32 + ln) * 4 + w) * 2) + half] = h;
            }
        }
        #pragma unroll
        for (int o = 16; o; o >>= 1) lacc += __shfl_xor_sync(0xFFFFFFFFu, lacc, o);
        if (lane == 0) red[wid] = lacc;
        __syncthreads();
        if (tid == 0) {
            double s = 0.0;
            #pragma unroll
            for (int w = 0; w < NWARPS; ++w) s += red[w];
            atomicAdd(&g_loss[lvl], s);
        }
        __syncthreads();
    }
}

__global__ void rvq_finalize_kernel(float* __restrict__ out, long long out_size) {
    long long ND = (long long)NROWS * DDIM;
    if (out_size <= ND) return;
    if (blockIdx.x == 0 && threadIdx.x == 0) {
        float loss = 0.f;
        for (int l = 0; l < LLEV; ++l) {
            float mean = (float)(g_loss[l] / (double)ND);
            loss = __fadd_rn(loss, __fmul_rn(0.25f, mean));
        }
        out[ND] = loss;
    }
}

extern "C" void kernel_launch(void* const* d_in, const int* in_sizes, int n_in,
                              void* d_out, int out_size)
{
    const float* x   = (const float*)d_in[0];
    const float* emb = (const float*)d_in[1];
    if (n_in >= 2 && in_sizes[0] == LLEV * KCODES * DDIM && in_sizes[1] == NROWS * DDIM) {
        const float* t = x; x = emb; emb = t;
    }
    float* out = (float*)d_out;
    long long osz = (long long)out_size;

    rvq_zero_kernel<<<1, 32>>>();
    rvq_packB_kernel<<<LLEV * 8 * 16, 128>>>(emb);
    rvq_norms_kernel<<<(LLEV * KCODES * 32) / 256, 256>>>(emb);

    cudaFuncSetAttribute(rvq_mma_kernel,
                         cudaFuncAttributeMaxDynamicSharedMemorySize, SMEM_BYTES);
    rvq_mma_kernel<<<NROWS / TILE_M, THREADS, SMEM_BYTES>>>(x, emb, out, osz);

    rvq_finalize_kernel<<<1, 32>>>(out, osz);
}

// round 17
// speedup vs baseline: 1.1106x; 1.1106x over previous
#include <cuda_runtime.h>
#include <cuda_bf16.h>
#include <stdint.h>

#define NROWS   65536
#define DDIM    256
#define KCODES  1024
#define LLEV    8
#define TILE_M  64
#define THREADS 256
#define NWARPS  8
#define CBUF    32
#define EPS     3e-3f
#define TSTRIDE 65

__device__ double g_loss[LLEV];
__device__ float  g_norms[LLEV * KCODES];
// fragment-linear bf16 codebook: [(lvl*8+pass)*16+ks][nfg*32+lane] uint2
__device__ __align__(16) uint2 g_B[(size_t)LLEV * 8 * 16 * 512];

// residual tile index (row r, dim dd) — conflict-free for all phases
#define TIX(r, dd) (((dd) * TSTRIDE) + (r) + ((((dd) >> 6) & 3) << 3))

// smem layout (bytes)
#define SM_A    0                     // 32768: A plane uint4[4*16*32]
#define SM_TILE 32768                 // 66816: float[DDIM*TSTRIDE+64]
#define SM_BS   99584                 // 4096
#define SM_AS   103680                // 256
#define SM_WMV  103936                // 1024: float[64][4]
#define SM_THR  104960                // 256
#define SM_CNT  105216                // 256
#define SM_CAND 105472                // 4096: uint16[64][32]
#define SM_BEST 109568                // 512: uint64[64]
#define SM_IDX  110080                // 256
#define SM_RED  110336                // 64
#define SMEM_BYTES 110400

__device__ __forceinline__ void mma16816(float* c, const uint4 a, const uint2 b) {
    asm volatile("mma.sync.aligned.m16n8k16.row.col.f32.bf16.bf16.f32 "
        "{%0,%1,%2,%3},{%4,%5,%6,%7},{%8,%9},{%0,%1,%2,%3};"
        : "+f"(c[0]), "+f"(c[1]), "+f"(c[2]), "+f"(c[3])
        : "r"(a.x), "r"(a.y), "r"(a.z), "r"(a.w), "r"(b.x), "r"(b.y));
}

// ---------------- prep ----------------
__global__ void rvq_zero_kernel() { if (threadIdx.x < LLEV) g_loss[threadIdx.x] = 0.0; }

__global__ void rvq_norms_kernel(const float* __restrict__ emb) {
    int warp = (blockIdx.x * blockDim.x + threadIdx.x) >> 5;
    int lane = threadIdx.x & 31;
    if (warp >= LLEV * KCODES) return;
    const float* e = emb + (size_t)warp * DDIM;
    float s = 0.f;
    #pragma unroll
    for (int i = 0; i < DDIM / 32; ++i) { float v = e[lane + 32 * i]; s = __fmaf_rn(v, v, s); }
    #pragma unroll
    for (int o = 16; o; o >>= 1) s += __shfl_xor_sync(0xFFFFFFFFu, s, o);
    if (lane == 0) g_norms[warp] = s;
}

__global__ void rvq_packB_kernel(const float* __restrict__ emb) {
    int b = blockIdx.x;                  // (lvl*8+p)*16+ks
    int lvl = b >> 7, p = (b >> 4) & 7, ks = b & 15;
    for (int pid = threadIdx.x; pid < 512; pid += blockDim.x) {
        int nf = pid >> 5, lane = pid & 31;
        int code = p * 128 + nf * 8 + (lane >> 2);
        int kb   = ks * 16 + 2 * (lane & 3);
        const float* e = emb + ((size_t)lvl * KCODES + code) * DDIM + kb;
        uint16_t h0 = __bfloat16_as_ushort(__float2bfloat16(e[0]));
        uint16_t h1 = __bfloat16_as_ushort(__float2bfloat16(e[1]));
        uint16_t h2 = __bfloat16_as_ushort(__float2bfloat16(e[8]));
        uint16_t h3 = __bfloat16_as_ushort(__float2bfloat16(e[9]));
        g_B[(size_t)b * 512 + nf * 32 + lane] =
            make_uint2((uint32_t)h0 | ((uint32_t)h1 << 16),
                       (uint32_t)h2 | ((uint32_t)h3 << 16));
    }
}

// ---------------- main ----------------
__global__ void __launch_bounds__(THREADS, 2)
rvq_mma_kernel(const float* __restrict__ x, const float* __restrict__ emb,
               float* __restrict__ out, long long out_size)
{
    extern __shared__ char smem[];
    uint4*     Ah   = (uint4*)(smem + SM_A);
    float*     T    = (float*)(smem + SM_TILE);
    float*     b_s  = (float*)(smem + SM_BS);
    float*     a_s  = (float*)(smem + SM_AS);
    float*     wmv  = (float*)(smem + SM_WMV);
    float*     thr_s = (float*)(smem + SM_THR);
    uint32_t*  cnt  = (uint32_t*)(smem + SM_CNT);
    uint16_t*  cand = (uint16_t*)(smem + SM_CAND);
    unsigned long long* best = (unsigned long long*)(smem + SM_BEST);
    int*       idx_s = (int*)(smem + SM_IDX);
    double*    red  = (double*)(smem + SM_RED);

    const int tid = threadIdx.x, wid = tid >> 5, lane = tid & 31;
    const int mg = wid & 1, ng = wid >> 1;       // 2 m-groups x 4 n-groups
    const int rowbase = blockIdx.x * TILE_M;
    const int d = tid;                           // split/update: dim
    const int di = d & 15, sk = d >> 4;
    const int lane_dp = (di & 7) >> 1, word_dp = 2 * (di >> 3), half = di & 1;

    // ---- lvl-0 load: x -> tile + A plane ----
    #pragma unroll 4
    for (int r = 0; r < TILE_M; ++r) {
        float v = x[(size_t)(rowbase + r) * DDIM + d];
        T[TIX(r, d)] = v;
        uint16_t h = __bfloat16_as_ushort(__float2bfloat16(v));
        int ri = r & 15, mtg = r >> 4;
        int ln = (ri & 7) * 4 + lane_dp;
        int w  = (ri >> 3) + word_dp;
        ((uint16_t*)Ah)[((((mtg * 16 + sk) * 32 + ln) * 4 + w) * 2) + half] = h;
    }
    __syncthreads();

    for (int lvl = 0; lvl < LLEV; ++lvl) {
        // ---- row norms from tile (bit-exact tree) ----
        {
            int r = tid >> 2, p = tid & 3;
            float s = 0.f;
            #pragma unroll 8
            for (int j = 0; j < 64; ++j) {
                float v = T[TIX(r, p * 64 + j)];
                s = __fmaf_rn(v, v, s);
            }
            s += __shfl_xor_sync(0xFFFFFFFFu, s, 1);
            s += __shfl_xor_sync(0xFFFFFFFFu, s, 2);
            if (p == 0) a_s[r] = s;
        }
        #pragma unroll
        for (int i = 0; i < KCODES / THREADS; ++i)
            b_s[tid + THREADS * i] = g_norms[lvl * KCODES + tid + THREADS * i];
        if (tid < TILE_M) { cnt[tid] = 0u; best[tid] = ~0ull; }
        __syncthreads();

        float a8[2][2];
        #pragma unroll
        for (int mt = 0; mt < 2; ++mt)
            #pragma unroll
            for (int h2 = 0; h2 < 2; ++h2)
                a8[mt][h2] = a_s[mg * 32 + mt * 16 + h2 * 8 + (lane >> 2)];

        // ======== PASS 1: GEMM, per-thread min (branchless fminf) ========
        float tmin[2][2];
        #pragma unroll
        for (int mt = 0; mt < 2; ++mt)
            #pragma unroll
            for (int h2 = 0; h2 < 2; ++h2) tmin[mt][h2] = 3.4028235e38f;

        for (int it = 0; it < 8; ++it) {
            float acc[2][4][4];
            #pragma unroll
            for (int a = 0; a < 2; ++a)
                #pragma unroll
                for (int b = 0; b < 4; ++b)
                    #pragma unroll
                    for (int c = 0; c < 4; ++c) acc[a][b][c] = 0.f;
            const uint2* gb = g_B + (size_t)((lvl * 8 + it) * 16) * 512;
            #pragma unroll 4
            for (int s = 0; s < 16; ++s) {
                uint4 ah[2];
                #pragma unroll
                for (int mt = 0; mt < 2; ++mt)
                    ah[mt] = Ah[((mg * 2 + mt) * 16 + s) * 32 + lane];
                const uint2* gs = gb + (size_t)s * 512;
                #pragma unroll
                for (int nf = 0; nf < 4; ++nf) {
                    uint2 bh = gs[(ng * 4 + nf) * 32 + lane];
                    mma16816(acc[0][nf], ah[0], bh);
                    mma16816(acc[1][nf], ah[1], bh);
                }
            }
            #pragma unroll
            for (int mt = 0; mt < 2; ++mt)
                #pragma unroll
                for (int h2 = 0; h2 < 2; ++h2) {
                    float m0 = tmin[mt][h2];
                    #pragma unroll
                    for (int nf = 0; nf < 4; ++nf) {
                        int k0 = it * 128 + ng * 32 + nf * 8 + 2 * (lane & 3);
                        float dA = __fmaf_rn(-2.0f, acc[mt][nf][h2 * 2],     __fadd_rn(a8[mt][h2], b_s[k0]));
                        float dB = __fmaf_rn(-2.0f, acc[mt][nf][h2 * 2 + 1], __fadd_rn(a8[mt][h2], b_s[k0 + 1]));
                        m0 = fminf(m0, fminf(dA, dB));
                    }
                    tmin[mt][h2] = m0;
                }
        }
        #pragma unroll
        for (int mt = 0; mt < 2; ++mt)
            #pragma unroll
            for (int h2 = 0; h2 < 2; ++h2) {
                float v = tmin[mt][h2];
                v = fminf(v, __shfl_xor_sync(0xFFFFFFFFu, v, 1));
                v = fminf(v, __shfl_xor_sync(0xFFFFFFFFu, v, 2));
                if ((lane & 3) == 0) {
                    int row = mg * 32 + mt * 16 + h2 * 8 + (lane >> 2);
                    wmv[row * 4 + ng] = v;
                }
            }
        __syncthreads();
        if (tid < TILE_M) {
            float v = fminf(fminf(wmv[tid * 4], wmv[tid * 4 + 1]),
                            fminf(wmv[tid * 4 + 2], wmv[tid * 4 + 3]));
            thr_s[tid] = v + EPS;
        }
        __syncthreads();

        // ======== PASS 2: GEMM again, append candidates under final threshold ========
        for (int it = 0; it < 8; ++it) {
            float acc[2][4][4];
            #pragma unroll
            for (int a = 0; a < 2; ++a)
                #pragma unroll
                for (int b = 0; b < 4; ++b)
                    #pragma unroll
                    for (int c = 0; c < 4; ++c) acc[a][b][c] = 0.f;
            const uint2* gb = g_B + (size_t)((lvl * 8 + it) * 16) * 512;
            #pragma unroll 4
            for (int s = 0; s < 16; ++s) {
                uint4 ah[2];
                #pragma unroll
                for (int mt = 0; mt < 2; ++mt)
                    ah[mt] = Ah[((mg * 2 + mt) * 16 + s) * 32 + lane];
                const uint2* gs = gb + (size_t)s * 512;
                #pragma unroll
                for (int nf = 0; nf < 4; ++nf) {
                    uint2 bh = gs[(ng * 4 + nf) * 32 + lane];
                    mma16816(acc[0][nf], ah[0], bh);
                    mma16816(acc[1][nf], ah[1], bh);
                }
            }
            #pragma unroll
            for (int mt = 0; mt < 2; ++mt)
                #pragma unroll
                for (int h2 = 0; h2 < 2; ++h2) {
                    int row = mg * 32 + mt * 16 + h2 * 8 + (lane >> 2);
                    float thr = thr_s[row];
                    #pragma unroll
                    for (int nf = 0; nf < 4; ++nf) {
                        int k0 = it * 128 + ng * 32 + nf * 8 + 2 * (lane & 3);
                        float dA = __fmaf_rn(-2.0f, acc[mt][nf][h2 * 2],     __fadd_rn(a8[mt][h2], b_s[k0]));
                        float dB = __fmaf_rn(-2.0f, acc[mt][nf][h2 * 2 + 1], __fadd_rn(a8[mt][h2], b_s[k0 + 1]));
                        if (dA <= thr) {
                            uint32_t pos = atomicAdd(&cnt[row], 1u);
                            if (pos < CBUF) cand[row * CBUF + pos] = (uint16_t)k0;
                        }
                        if (dB <= thr) {
                            uint32_t pos = atomicAdd(&cnt[row], 1u);
                            if (pos < CBUF) cand[row * CBUF + pos] = (uint16_t)(k0 + 1);
                        }
                    }
                }
        }
        __syncthreads();

        // ---- exact refine (R13-proven): lane = candidate, serial ascending fp32 chain ----
        const float* Eb = emb + (size_t)lvl * KCODES * DDIM;
        for (int row = wid; row < TILE_M; row += NWARPS) {
            uint32_t n = cnt[row];
            float ar = a_s[row];
            unsigned long long bp = ~0ull;
            if (n <= CBUF) {
                for (uint32_t c = lane; c < n; c += 32) {
                    int k = cand[row * CBUF + c];
                    const float4* e4 = (const float4*)(Eb + (size_t)k * DDIM);
                    float s = 0.f;
                    #pragma unroll 8
                    for (int q = 0; q < DDIM / 4; ++q) {
                        float4 ev = e4[q];
                        s = __fmaf_rn(T[TIX(row, 4 * q + 0)], ev.x, s);
                        s = __fmaf_rn(T[TIX(row, 4 * q + 1)], ev.y, s);
                        s = __fmaf_rn(T[TIX(row, 4 * q + 2)], ev.z, s);
                        s = __fmaf_rn(T[TIX(row, 4 * q + 3)], ev.w, s);
                    }
                    float dist = __fmaf_rn(-2.0f, s, __fadd_rn(ar, b_s[k]));
                    unsigned long long p = ((unsigned long long)__float_as_uint(dist) << 32) | (uint32_t)k;
                    if (p < bp) bp = p;
                }
            } else {
                for (int k = lane; k < KCODES; k += 32) {
                    const float4* e4 = (const float4*)(Eb + (size_t)k * DDIM);
                    float s = 0.f;
                    #pragma unroll 8
                    for (int q = 0; q < DDIM / 4; ++q) {
                        float4 ev = e4[q];
                        s = __fmaf_rn(T[TIX(row, 4 * q + 0)], ev.x, s);
                        s = __fmaf_rn(T[TIX(row, 4 * q + 1)], ev.y, s);
                        s = __fmaf_rn(T[TIX(row, 4 * q + 2)], ev.z, s);
                        s = __fmaf_rn(T[TIX(row, 4 * q + 3)], ev.w, s);
                    }
                    float dist = __fmaf_rn(-2.0f, s, __fadd_rn(ar, b_s[k]));
                    unsigned long long p = ((unsigned long long)__float_as_uint(dist) << 32) | (uint32_t)k;
                    if (p < bp) bp = p;
                }
            }
            #pragma unroll
            for (int o = 16; o; o >>= 1) {
                unsigned long long op = __shfl_xor_sync(0xFFFFFFFFu, bp, o);
                if (op < bp) bp = op;
            }
            if (lane == 0) best[row] = bp;
        }
        __syncthreads();

        if (tid < TILE_M) {
            int ix = (int)(uint32_t)(best[tid] & 0xFFFFFFFFu);
            idx_s[tid] = ix;
            long long ib = (long long)NROWS * DDIM + 1 +
                           ((long long)(rowbase + tid) * LLEV + lvl);
            if (ib < out_size) out[ib] = (float)ix;
        }
        __syncthreads();

        // ---- update (exact fp32 chain) fused with next level's split ----
        double lacc = 0.0;
        const bool more = (lvl + 1 < LLEV);
        #pragma unroll 4
        for (int r = 0; r < TILE_M; ++r) {
            int code = idx_s[r];
            float q  = Eb[(size_t)code * DDIM + d];
            float rv = T[TIX(r, d)];
            float df = __fsub_rn(q, rv);
            float qs = __fadd_rn(rv, df);
            lacc = __fma_rn((double)df, (double)df, lacc);
            float nr = __fsub_rn(rv, qs);
            T[TIX(r, d)] = nr;
            size_t off = (size_t)(rowbase + r) * DDIM + d;
            out[off] = lvl ? __fadd_rn(out[off], qs) : qs;
            if (more) {
                uint16_t h = __bfloat16_as_ushort(__float2bfloat16(nr));
                int ri = r & 15, mtg = r >> 4;
                int ln = (ri & 7) * 4 + lane_dp;
                int w  = (ri >> 3) + word_dp;
                ((uint16_t*)Ah)[((((mtg * 16 + sk) * 32 + ln) * 4 + w) * 2) + half] = h;
            }
        }
        #pragma unroll
        for (int o = 16; o; o >>= 1) lacc += __shfl_xor_sync(0xFFFFFFFFu, lacc, o);
        if (lane == 0) red[wid] = lacc;
        __syncthreads();
        if (tid == 0) {
            double s = 0.0;
            #pragma unroll
            for (int w = 0; w < NWARPS; ++w) s += red[w];
            atomicAdd(&g_loss[lvl], s);
        }
        __syncthreads();
    }
}

__global__ void rvq_finalize_kernel(float* __restrict__ out, long long out_size) {
    long long ND = (long long)NROWS * DDIM;
    if (out_size <= ND) return;
    if (blockIdx.x == 0 && threadIdx.x == 0) {
        float loss = 0.f;
        for (int l = 0; l < LLEV; ++l) {
            float mean = (float)(g_loss[l] / (double)ND);
            loss = __fadd_rn(loss, __fmul_rn(0.25f, mean));
        }
        out[ND] = loss;
    }
}

extern "C" void kernel_launch(void* const* d_in, const int* in_sizes, int n_in,
                              void* d_out, int out_size)
{
    const float* x   = (const float*)d_in[0];
    const float* emb = (const float*)d_in[1];
    if (n_in >= 2 && in_sizes[0] == LLEV * KCODES * DDIM && in_sizes[1] == NROWS * DDIM) {
        const float* t = x; x = emb; emb = t;
    }
    float* out = (float*)d_out;
    long long osz = (long long)out_size;

    rvq_zero_kernel<<<1, 32>>>();
    rvq_packB_kernel<<<LLEV * 8 * 16, 128>>>(emb);
    rvq_norms_kernel<<<(LLEV * KCODES * 32) / 256, 256>>>(emb);

    cudaFuncSetAttribute(rvq_mma_kernel,
                         cudaFuncAttributeMaxDynamicSharedMemorySize, SMEM_BYTES);
    rvq_mma_kernel<<<NROWS / TILE_M, THREADS, SMEM_BYTES>>>(x, emb, out, osz);

    rvq_finalize_kernel<<<1, 32>>>(out, osz);
}